// round 12
// baseline (speedup 1.0000x reference)
#include <cuda_runtime.h>
#include <cuda_bf16.h>

// PartialMatchingLoss: mean over partial points of min Euclidean distance to
// completed points (per batch). B=8, M=4096, N=8192, D=3.
//
// min_n d^2 = ||p||^2 + min_n (||c||^2 - 2 p.c)   (psq folded in before merge)
// k1: packed-completed-point hot loop (fma.rn.f32x2, 2 points per instr);
//     per-query min merged across N-splits via atomicMax on a descending-
//     sortable uint key (exact, commutative -> deterministic; 0 = identity).
// k2: key-only pass: decode, sqrt, deterministic sum; resets keys+counter so
//     every graph replay starts from identical state.

#define B_ 8
#define M_ 4096
#define N_ 8192

#define THREADS 128
#define Q 4                          // queries per thread
#define MCHUNK (THREADS * Q)         // 512 queries per CTA
#define NMCHUNK (M_ / MCHUNK)        // 8
#define NSPLIT 16
#define NTILE (N_ / NSPLIT)          // 512 completed points per tile
#define NGROUP (NTILE / 2)           // 256 packed point-pairs
#define K1_GRID (B_ * NMCHUNK * NSPLIT) // 1024 CTAs -> single wave at 8/SM

#define TOTAL_P (B_ * M_)            // 32768
#define K2_THREADS 256
#define K2_CTAS 32                   // 32*256*4 keys = 32768

// Scratch (no allocation allowed). g_key zero-init by runtime = identity for
// the max-merge; k2 resets it to 0 each launch. g_cnt reset each launch.
__device__ unsigned int g_key[TOTAL_P];       // 128 KB
__device__ float g_blocksum[K2_CTAS];
__device__ unsigned int g_cnt;

#define FMA_F32X2(d, a, b, c) \
    asm("fma.rn.f32x2 %0, %1, %2, %3;" : "=l"(d) : "l"(a), "l"(b), "l"(c))

__device__ __forceinline__ unsigned long long pk2(float a, float b) {
    unsigned long long r;
    asm("mov.b64 %0, {%1, %2};" : "=l"(r) : "f"(a), "f"(b));
    return r;
}
__device__ __forceinline__ void unpk2(float& lo, float& hi, unsigned long long v) {
    asm("mov.b64 {%0, %1}, %2;" : "=f"(lo), "=f"(hi) : "l"(v));
}

// Descending-sortable encoding: key strictly DECREASES as f increases and
// key(any finite f) > 0, so atomicMax(key) == min(f) and 0 is the identity.
__device__ __forceinline__ unsigned int enc_desc(float f) {
    unsigned int u = __float_as_uint(f);
    unsigned int mask = ((unsigned int)((int)u >> 31)) | 0x80000000u;
    return ~(u ^ mask);
}
__device__ __forceinline__ float dec_desc(unsigned int key) {
    unsigned int s = ~key;
    unsigned int mask = (~((unsigned int)((int)s >> 31))) | 0x80000000u;
    return __uint_as_float(s ^ mask);
}

__global__ void __launch_bounds__(THREADS, 8)   // 64-reg ceiling, 8 CTAs/SM
k1_min_tile(const float* __restrict__ completed, const float* __restrict__ partial) {
    // Group g (points 2g, 2g+1):
    //   sxy[g] = { {x,x'}, {y,y'} },  szw[g] = { {z,z'}, {w,w'} }  (w = ||c||^2)
    __shared__ ulonglong2 sxy[NGROUP];   // 4 KB
    __shared__ ulonglong2 szw[NGROUP];   // 4 KB

    const int bid = blockIdx.x;
    const int ns  = bid & (NSPLIT - 1);
    const int r   = bid >> 4;
    const int mc  = r & (NMCHUNK - 1);
    const int b   = r >> 3;
    const int tid = threadIdx.x;

    // Stage tile: 2 passes of 128 point-pairs.
    {
        const float* cg = completed + ((size_t)b * N_ + (size_t)ns * NTILE) * 3;
#pragma unroll
        for (int g = tid; g < NGROUP; g += THREADS) {
            const float* p2 = cg + 6 * g;
            float x0 = p2[0], y0 = p2[1], z0 = p2[2];
            float x1 = p2[3], y1 = p2[4], z1 = p2[5];
            float w0 = fmaf(x0, x0, fmaf(y0, y0, z0 * z0));
            float w1 = fmaf(x1, x1, fmaf(y1, y1, z1 * z1));
            sxy[g] = make_ulonglong2(pk2(x0, x1), pk2(y0, y1));
            szw[g] = make_ulonglong2(pk2(z0, z1), pk2(w0, w1));
        }
    }

    // Queries: -2*p duplicated into packed registers; keep ||p||^2 per query.
    const int m0 = mc * MCHUNK;
    unsigned long long qx[Q], qy[Q], qz[Q];
    float psq[Q], mnE[Q], mnO[Q];
#pragma unroll
    for (int t = 0; t < Q; t++) {
        const float* pg = partial + ((size_t)b * M_ + m0 + tid + t * THREADS) * 3;
        float px = pg[0], py = pg[1], pz = pg[2];
        psq[t] = fmaf(px, px, fmaf(py, py, pz * pz));
        float vx = -2.0f * px, vy = -2.0f * py, vz = -2.0f * pz;
        qx[t] = pk2(vx, vx);
        qy[t] = pk2(vy, vy);
        qz[t] = pk2(vz, vz);
        mnE[t] = 3.4e38f;
        mnO[t] = 3.4e38f;
    }
    __syncthreads();

    // Hot loop: per group (2 points): 2 LDS.128 + Q*(3 FFMA2 + 2 FMNMX).
    // All lanes read the same smem address -> broadcast, conflict-free.
#pragma unroll 4
    for (int g = 0; g < NGROUP; g++) {
        ulonglong2 A = sxy[g];   // {xx', yy'}
        ulonglong2 Bv = szw[g];  // {zz', ww'}
#pragma unroll
        for (int t = 0; t < Q; t++) {
            unsigned long long acc;
            FMA_F32X2(acc, qz[t], Bv.x, Bv.y);
            FMA_F32X2(acc, qy[t], A.y, acc);
            FMA_F32X2(acc, qx[t], A.x, acc);
            float lo, hi;
            unpk2(lo, hi, acc);
            mnE[t] = fminf(mnE[t], lo);   // even-point chain
            mnO[t] = fminf(mnO[t], hi);   // odd-point chain (independent)
        }
    }

    // Fold psq, then merge across N-splits: exact, order-invariant.
#pragma unroll
    for (int t = 0; t < Q; t++) {
        unsigned int key = enc_desc(psq[t] + fminf(mnE[t], mnO[t]));
        atomicMax(&g_key[b * M_ + m0 + tid + t * THREADS], key);
    }
}

// k2: keys -> distances -> deterministic sum. Each thread handles 4 keys via
// one uint4 load (L2-resident), then resets them. Last-arriving CTA sums the
// 32 block results in fixed order and resets the counter.
__global__ void __launch_bounds__(K2_THREADS)
k2_reduce(float* __restrict__ out) {
    __shared__ float ssum[K2_THREADS];
    __shared__ int is_last;
    const int tid = threadIdx.x;
    const int idx = blockIdx.x * K2_THREADS + tid;   // uint4 index

    uint4 k = ((const uint4*)g_key)[idx];
    ((uint4*)g_key)[idx] = make_uint4(0u, 0u, 0u, 0u);  // restore identity

    float d0 = sqrtf(fmaxf(dec_desc(k.x), 0.0f));
    float d1 = sqrtf(fmaxf(dec_desc(k.y), 0.0f));
    float d2 = sqrtf(fmaxf(dec_desc(k.z), 0.0f));
    float d3 = sqrtf(fmaxf(dec_desc(k.w), 0.0f));

    ssum[tid] = (d0 + d1) + (d2 + d3);
    __syncthreads();
#pragma unroll
    for (int off = K2_THREADS / 2; off > 0; off >>= 1) {
        if (tid < off) ssum[tid] += ssum[tid + off];
        __syncthreads();
    }
    if (tid == 0) {
        g_blocksum[blockIdx.x] = ssum[0];
        __threadfence();
        unsigned int ticket = atomicAdd(&g_cnt, 1u);
        is_last = (ticket == K2_CTAS - 1);
    }
    __syncthreads();

    if (is_last) {
        // All other CTAs' g_blocksum writes are visible (their fence precedes
        // the ticket that made us last).
        if (tid < K2_CTAS) ssum[tid] = g_blocksum[tid];
        __syncthreads();
        if (tid == 0) {
            float s = 0.0f;
#pragma unroll
            for (int i = 0; i < K2_CTAS; i++) s += ssum[i];   // fixed order
            out[0] = s * (1.0f / (float)TOTAL_P);
            g_cnt = 0;  // restore for the next graph replay
        }
    }
}

extern "C" void kernel_launch(void* const* d_in, const int* in_sizes, int n_in,
                              void* d_out, int out_size) {
    const float* completed = (const float*)d_in[0];  // (8, 8192, 3)
    const float* partial   = (const float*)d_in[1];  // (8, 4096, 3)
    if (n_in >= 2 && in_sizes[0] == B_ * M_ * 3 && in_sizes[1] == B_ * N_ * 3) {
        completed = (const float*)d_in[1];
        partial   = (const float*)d_in[0];
    }

    k1_min_tile<<<K1_GRID, THREADS>>>(completed, partial);
    k2_reduce<<<K2_CTAS, K2_THREADS>>>((float*)d_out);
}